// round 14
// baseline (speedup 1.0000x reference)
#include <cuda_runtime.h>
#include <math.h>

#define T_LEN  480000
#define B_ROWS 64
#define B_HALF 32
#define NTHR   256

// RN(1/16000): matches XLA's divide->multiply-by-reciprocal rewrite.
// Load-bearing for correctness (round-4 win) -- do not change.
#define INV_SR 6.25e-5f

// ---------------------------------------------------------------------------
// Sine = exact Cody-Waite mod-2pi reduction + MUFU sin on r in [-pi, pi].
// Validated round 13 (rel_err 5.47e-4). BIT-IDENTICAL -- do not change.
// ---------------------------------------------------------------------------
__device__ __forceinline__ float sin_fast(float x)
{
    const float MAGIC = 12582912.0f;                   // 1.5 * 2^23
    float jf = __fmaf_rn(x, 0.15915494309189533577f, MAGIC);  // round(x/2pi)
    float n  = __fsub_rn(jf, MAGIC);

    float r = __fmaf_rn(n, -6.28318548202514648438f, x);
    r = __fmaf_rn(n, 1.74845560007442631e-7f, r);      // +n*(hi - 2pi)

    float s;
    asm("sin.approx.f32 %0, %1;" : "=f"(s) : "f"(r));  // MUFU on reduced arg
    return s;
}

// delay + gather index for one sample. Scalar chain bit-identical to round 13.
template<bool CHECK>
__device__ __forceinline__ void delay_calc(
    float posf, float t, float4 p, float& rp, int& il, float& frac)
{
    const float arg = __fmul_rn(p.x, t);               // ref f32 op order
    const float lfo = sin_fast(arg);
    float delay = __fadd_rn(p.z, __fmul_rn(__fmul_rn(lfo, p.y), p.z));
    delay = fminf(fmaxf(delay, 1.0f), 800.0f);
    rp = __fsub_rn(posf, delay);                       // ref's f32 quantization
    il = __float2int_rd(rp);
    if (CHECK) il = max(il, 0);
    frac = __fsub_rn(rp, floorf(rp));
}

// 2 adjacent samples (i0 even, i0+1) x B_HALF batches per thread.
// Mem ops per sample: 3.5 (vs 5 scalar) -- LSU is the round-13 co-limiter.
template<bool CHECK>
__device__ __forceinline__ void chorus_body(
    const float* __restrict__ audio, float* __restrict__ out,
    const float4* __restrict__ s_p, int i0)
{
    const float posf0 = (float)i0;                     // exact (i < 2^24)
    const float posf1 = (float)(i0 + 1);
    const float t0 = __fmul_rn(posf0, INV_SR);         // XLA reciprocal-mul
    const float t1 = __fmul_rn(posf1, INV_SR);

    const float* row  = audio;
    float*       orow = out;

    #pragma unroll 2
    for (int b = 0; b < B_HALF; ++b, row += T_LEN, orow += T_LEN) {
        const float4 p = s_p[b];                       // one LDS.128, 2 samples

        float rp0, frac0, rp1, frac1; int il0, il1;
        delay_calc<CHECK>(posf0, t0, p, rp0, il0, frac0);
        delay_calc<CHECK>(posf1, t1, p, rp1, il1, frac1);

        // x for both samples in one aligned 64-bit load (i0 even).
        const float2 x2 = *reinterpret_cast<const float2*>(row + i0);

        const float a00 = __ldg(row + il0);
        const float a01 = __ldg(row + il0 + 1);
        const float a10 = __ldg(row + il1);
        const float a11 = __ldg(row + il1 + 1);

        float d0 = __fmaf_rn(frac0, __fsub_rn(a01, a00), a00);
        float d1 = __fmaf_rn(frac1, __fsub_rn(a11, a10), a10);
        if (CHECK) {
            d0 = (rp0 >= 0.0f) ? d0 : 0.0f;
            d1 = (rp1 >= 0.0f) ? d1 : 0.0f;
        }

        float2 o;
        o.x = __fmaf_rn(p.w, __fsub_rn(d0, x2.x), x2.x);  // x + m*(d-x)
        o.y = __fmaf_rn(p.w, __fsub_rn(d1, x2.y), x2.y);
        *reinterpret_cast<float2*>(orow + i0) = o;        // one 64-bit store
    }
}

__global__ __launch_bounds__(NTHR, 8)    // force <=32 regs -> 8 blocks/SM
void chorus_kernel(const float* __restrict__ audio,
                   const float* __restrict__ rate_hz,
                   const float* __restrict__ depth,
                   const float* __restrict__ centre_ms,
                   const float* __restrict__ mix,
                   float* __restrict__ out)
{
    __shared__ float4 s_p[B_HALF];                     // this block's 32 batches

    const int b_base = blockIdx.y * B_HALF;            // batch half split on y
    const float TWO_PI_F = 6.28318530717958647692f;    // f32 = 0x40C90FDB
    if (threadIdx.x < B_HALF) {
        const int b = b_base + threadIdx.x;
        float4 p;
        p.x = __fmul_rn(TWO_PI_F, __ldg(rate_hz + b));
        p.y = __ldg(depth + b);
        p.z = __fmul_rn(__ldg(centre_ms + b), 16.0f);
        p.w = __ldg(mix + b);
        s_p[threadIdx.x] = p;
    }
    __syncthreads();

    const int i0 = (blockIdx.x * NTHR + threadIdx.x) * 2;
    if (i0 >= T_LEN) return;

    const float* audio_h = audio + (size_t)b_base * T_LEN;
    float*       out_h   = out   + (size_t)b_base * T_LEN;

    // Block-uniform specialization: bx >= 2 -> i0 >= 1024 -> rp, il in range.
    if (blockIdx.x >= 2) chorus_body<false>(audio_h, out_h, s_p, i0);
    else                 chorus_body<true >(audio_h, out_h, s_p, i0);
}

extern "C" void kernel_launch(void* const* d_in, const int* in_sizes, int n_in,
                              void* d_out, int out_size)
{
    // metadata order: audio, rate_hz, depth, centre_delay_ms, feedback(unused), mix
    const float* audio     = (const float*)d_in[0];
    const float* rate_hz   = (const float*)d_in[1];
    const float* depth     = (const float*)d_in[2];
    const float* centre_ms = (const float*)d_in[3];
    const float* mix       = (const float*)d_in[5];
    float* out = (float*)d_out;

    (void)in_sizes; (void)n_in; (void)out_size;

    dim3 grid((T_LEN / 2 + NTHR - 1) / NTHR, 2);       // 938 x 2 blocks
    chorus_kernel<<<grid, NTHR>>>(audio, rate_hz, depth, centre_ms, mix, out);
}

// round 15
// speedup vs baseline: 1.0046x; 1.0046x over previous
#include <cuda_runtime.h>
#include <math.h>

#define T_LEN  480000
#define B_ROWS 64

// RN(1/16000): matches XLA's divide->multiply-by-reciprocal rewrite.
// Load-bearing for correctness (round-4 win) -- do not change.
#define INV_SR 6.25e-5f

// ---------------------------------------------------------------------------
// Sine = exact Cody-Waite mod-2pi reduction + MUFU sin on r in [-pi, pi].
// Validated rounds 13/14 (rel_err 5.47e-4). BIT-IDENTICAL -- do not change.
// ---------------------------------------------------------------------------
__device__ __forceinline__ float sin_fast(float x)
{
    const float MAGIC = 12582912.0f;                   // 1.5 * 2^23
    float jf = __fmaf_rn(x, 0.15915494309189533577f, MAGIC);  // round(x/2pi)
    float n  = __fsub_rn(jf, MAGIC);

    float r = __fmaf_rn(n, -6.28318548202514648438f, x);
    r = __fmaf_rn(n, 1.74845560007442631e-7f, r);      // +n*(hi - 2pi)

    float s;
    asm("sin.approx.f32 %0, %1;" : "=f"(s) : "f"(r));  // MUFU on reduced arg
    return s;
}

// One (i,b) sample. CHECK=false: i >= 1024 > 800 >= delay proves rp >= 0 and
// il >= 0; skip the clamp + select.
template<bool CHECK>
__device__ __forceinline__ float chorus_sample(
    const float* __restrict__ row, int i, float posf, float t, float4 p)
{
    // arg = ((2*pi)*rate) * t -- exact reference f32 op order (p.x = 2pi*rate).
    const float arg = __fmul_rn(p.x, t);
    const float lfo = sin_fast(arg);

    // delay = cds + ((lfo*depth)*cds) -- exact ref rounding order.
    // Upper clip is DEAD: cds <= 400 and |lfo*depth| <= 1 -> delay <= 800 = MAX,
    // and clamping at equality is an identity. Lower clip (1.0) can bind.
    float delay = __fadd_rn(p.z, __fmul_rn(__fmul_rn(lfo, p.y), p.z));
    delay = fmaxf(delay, 1.0f);

    const float rp = __fsub_rn(posf, delay);           // ref's f32 quantization
    int il = __float2int_rd(rp);
    if (CHECK) il = max(il, 0);
    const float frac = __fsub_rn(rp, floorf(rp));

    const float a0 = __ldg(row + il);
    const float a1 = __ldg(row + il + 1);
    const float x  = __ldg(row + i);

    float delayed = __fmaf_rn(frac, __fsub_rn(a1, a0), a0);
    if (CHECK) delayed = (rp >= 0.0f) ? delayed : 0.0f;

    // x*(1-m) + d*m == x + m*(d-x); ±1ulp direct error, un-amplified.
    return __fmaf_rn(p.w, __fsub_rn(delayed, x), x);
}

template<bool CHECK>
__device__ __forceinline__ void chorus_body(
    const float* __restrict__ audio, float* __restrict__ out,
    const float4* __restrict__ s_p, int i)
{
    const float posf = (float)i;                       // exact (i < 2^24)
    const float t = __fmul_rn(posf, INV_SR);           // XLA reciprocal-mul

    const float* row  = audio;
    float*       orow = out;

    // unroll 8: more independent gather chains in flight per warp (issue was
    // 56% at unroll 4 -- latency exposure). MUFU sine body is small enough to
    // hold the 32-reg cap from __launch_bounds__(256, 8).
    #pragma unroll 8
    for (int b = 0; b < B_ROWS; ++b, row += T_LEN, orow += T_LEN) {
        const float4 p = s_p[b];                       // one LDS.128 broadcast
        orow[i] = chorus_sample<CHECK>(row, i, posf, t, p);
    }
}

__global__ __launch_bounds__(256, 8)   // force <=32 regs -> 8 blocks/SM
void chorus_kernel(const float* __restrict__ audio,
                   const float* __restrict__ rate_hz,
                   const float* __restrict__ depth,
                   const float* __restrict__ centre_ms,
                   const float* __restrict__ mix,
                   float* __restrict__ out)
{
    __shared__ float4 s_p[B_ROWS];                     // {2pi*rate, depth, cds, mix}

    const float TWO_PI_F = 6.28318530717958647692f;    // f32 = 0x40C90FDB
    if (threadIdx.x < B_ROWS) {
        const int b = threadIdx.x;
        float4 p;
        p.x = __fmul_rn(TWO_PI_F, __ldg(rate_hz + b));
        p.y = __ldg(depth + b);
        p.z = __fmul_rn(__ldg(centre_ms + b), 16.0f);
        p.w = __ldg(mix + b);
        s_p[b] = p;
    }
    __syncthreads();

    const int i = blockIdx.x * blockDim.x + threadIdx.x;
    if (i >= T_LEN) return;

    // Block-uniform specialization: bid >= 4 -> i >= 1024 -> rp, il in range.
    if (blockIdx.x >= 4) chorus_body<false>(audio, out, s_p, i);
    else                 chorus_body<true >(audio, out, s_p, i);
}

extern "C" void kernel_launch(void* const* d_in, const int* in_sizes, int n_in,
                              void* d_out, int out_size)
{
    // metadata order: audio, rate_hz, depth, centre_delay_ms, feedback(unused), mix
    const float* audio     = (const float*)d_in[0];
    const float* rate_hz   = (const float*)d_in[1];
    const float* depth     = (const float*)d_in[2];
    const float* centre_ms = (const float*)d_in[3];
    const float* mix       = (const float*)d_in[5];
    float* out = (float*)d_out;

    (void)in_sizes; (void)n_in; (void)out_size;

    const int threads = 256;
    const int blocks  = (T_LEN + threads - 1) / threads;   // 1875
    chorus_kernel<<<blocks, threads>>>(audio, rate_hz, depth, centre_ms, mix, out);
}